// round 9
// baseline (speedup 1.0000x reference)
#include <cuda_runtime.h>
#include <cuda_bf16.h>
#include <cstdint>

#define N_NODES 100000
#define N_EDGES 2000000
#define DIM 64
#define CAP 96   // max in-degree capacity (deg ~ Poisson(20); P(max>96) ~ 0)

#define AS_W 132                 // padded As row width (floats); 132%32=4 -> 2-way STS conflicts
#define NODES_PER_BLK 128

typedef unsigned long long ull;

// Scratch (no cudaMalloc allowed)
__device__ int g_cnt[N_NODES];
__device__ __align__(16) int g_adj[(size_t)N_NODES * CAP];          // 38.4 MB
__device__ __align__(16) float g_h1[(size_t)N_NODES * DIM];

// ---- f32x2 packed-FMA helpers (sm_103a) -----------------------------------
__device__ __forceinline__ ull rep2(float x) {
    ull r; asm("mov.b64 %0, {%1, %1};" : "=l"(r) : "f"(x)); return r;
}
__device__ __forceinline__ void fma2(ull& d, ull a, ull b) {
    asm("fma.rn.f32x2 %0, %1, %2, %0;" : "+l"(d) : "l"(a), "l"(b));
}
__device__ __forceinline__ float2 unpack2(ull v) {
    float2 f; asm("mov.b64 {%0, %1}, %2;" : "=f"(f.x), "=f"(f.y) : "l"(v)); return f;
}

// ---------------------------------------------------------------------------
// Build per-destination adjacency buckets: g_adj[dst*CAP + slot] = src.
// ---------------------------------------------------------------------------
__global__ void __launch_bounds__(256)
build_adj_kernel(const int* __restrict__ ei)
{
    unsigned e0 = (blockIdx.x * blockDim.x + threadIdx.x) * 4;
    if (e0 >= N_EDGES) return;
    int4 s4 = *reinterpret_cast<const int4*>(ei + e0);
    int4 d4 = *reinterpret_cast<const int4*>(ei + N_EDGES + e0);
    int ss[4] = {s4.x, s4.y, s4.z, s4.w};
    int dd[4] = {d4.x, d4.y, d4.z, d4.w};
    #pragma unroll
    for (int i = 0; i < 4; i++) {
        int slot = atomicAdd(&g_cnt[dd[i]], 1);
        if (slot < CAP) g_adj[(size_t)dd[i] * CAP + slot] = ss[i];
    }
}

// ---------------------------------------------------------------------------
// Fused layer: per block of 128 nodes,
//   Phase A: stage permuted W into Bs; gather neighbor means DIRECTLY into the
//            transposed As tile (k-rows permuted: feature 4c+i -> row 16i+c,
//            same permutation applied to W rows, so the GEMM sum is unchanged).
//   Phase B: register-tiled GEMM, 256 threads, 4 nodes x 8 cols each, f32x2.
// Two blocks co-reside per SM (100KB smem) so Phase B of one block overlaps
// Phase A (L2-bound) of the other.
// ---------------------------------------------------------------------------
template <bool RELU>
__global__ void __launch_bounds__(256)
fused_layer_kernel(const float* __restrict__ h,
                   const float* __restrict__ W,
                   const float* __restrict__ b,
                   float* __restrict__ out)
{
    extern __shared__ float smem[];
    float* As = smem;                       // [128 k][AS_W] (132-padded)
    float* Bs = smem + 128 * AS_W;          // [128 k][64 col] permuted rows
    __shared__ float bs[64];

    const int tid = threadIdx.x;
    const int base = blockIdx.x * NODES_PER_BLK;

    // ---- Stage W (k-rows permuted to match gather's transposed writes) ----
    {
        // row r (= blk*64 + 16i + c) <- W row (blk*64 + 4c + i); 2 threads/row
        int r = tid >> 1;
        int hr = tid & 1;
        int blk = (r & 64);
        int rr = r & 63;
        int i = rr >> 4;
        int c = rr & 15;
        int src = blk + 4 * c + i;
        const float4* W4 = reinterpret_cast<const float4*>(W);
        float4* Bs4w = reinterpret_cast<float4*>(Bs);
        #pragma unroll
        for (int q = 0; q < 8; q++)
            Bs4w[r * 16 + hr * 8 + q] = W4[src * 16 + hr * 8 + q];
        if (tid < 64) bs[tid] = b[tid];
    }

    // ---- Gather into As (warp per node stream; 16 nodes per warp) ----
    {
        const int lane = tid & 31;
        const int half = lane >> 4;
        const int sub  = lane & 15;
        const int warp = tid >> 5;
        const float4* __restrict__ h4 = reinterpret_cast<const float4*>(h);

        for (int nl = warp * 16; nl < warp * 16 + 16; nl++) {
            int node = base + nl;
            if (node >= N_NODES) break;

            const int deg = g_cnt[node];
            const int cnt = min(deg, CAP);
            const int* __restrict__ adj = g_adj + node * CAP;

            // self features: feature 4*sub+i -> As row 16i+sub
            if (half == 0) {
                float4 sv = h4[(size_t)node * 16 + sub];
                As[(sub)      * AS_W + nl] = sv.x;
                As[(16 + sub) * AS_W + nl] = sv.y;
                As[(32 + sub) * AS_W + nl] = sv.z;
                As[(48 + sub) * AS_W + nl] = sv.w;
            }

            float4 acc = make_float4(0.f, 0.f, 0.f, 0.f);
            int j = 0;
            for (; j + 8 <= cnt; j += 8) {
                int4 ia = *reinterpret_cast<const int4*>(adj + j);
                int4 ib = *reinterpret_cast<const int4*>(adj + j + 4);
                int s0 = half ? ia.y : ia.x;
                int s1 = half ? ia.w : ia.z;
                int s2 = half ? ib.y : ib.x;
                int s3 = half ? ib.w : ib.z;
                float4 v0 = h4[s0 * 16 + sub];
                float4 v1 = h4[s1 * 16 + sub];
                float4 v2 = h4[s2 * 16 + sub];
                float4 v3 = h4[s3 * 16 + sub];
                acc.x += (v0.x + v1.x) + (v2.x + v3.x);
                acc.y += (v0.y + v1.y) + (v2.y + v3.y);
                acc.z += (v0.z + v1.z) + (v2.z + v3.z);
                acc.w += (v0.w + v1.w) + (v2.w + v3.w);
            }
            for (; j + 2 <= cnt; j += 2) {
                int2 ia = *reinterpret_cast<const int2*>(adj + j);
                int s = half ? ia.y : ia.x;
                float4 v = h4[s * 16 + sub];
                acc.x += v.x; acc.y += v.y; acc.z += v.z; acc.w += v.w;
            }
            if (j < cnt && half == 0) {
                float4 v = h4[adj[j] * 16 + sub];
                acc.x += v.x; acc.y += v.y; acc.z += v.z; acc.w += v.w;
            }

            acc.x += __shfl_xor_sync(0xffffffffu, acc.x, 16);
            acc.y += __shfl_xor_sync(0xffffffffu, acc.y, 16);
            acc.z += __shfl_xor_sync(0xffffffffu, acc.z, 16);
            acc.w += __shfl_xor_sync(0xffffffffu, acc.w, 16);

            if (half == 0) {
                float inv = 1.0f / fmaxf((float)deg, 1.0f);
                // agg feature 4*sub+i -> As row 64 + 16i + sub
                As[(64 + sub)      * AS_W + nl] = acc.x * inv;
                As[(64 + 16 + sub) * AS_W + nl] = acc.y * inv;
                As[(64 + 32 + sub) * AS_W + nl] = acc.z * inv;
                As[(64 + 48 + sub) * AS_W + nl] = acc.w * inv;
            }
        }
    }
    __syncthreads();

    // ---- GEMM: 4 nodes x 8 cols per thread, f32x2 accumulators ----
    const int tx = tid & 31;    // node group (4 nodes)
    const int ty = tid >> 5;    // col group (8 cols), warp-uniform -> B broadcast

    const ulonglong2* __restrict__ Asu = reinterpret_cast<const ulonglong2*>(As);
    const float4* __restrict__ Bs4 = reinterpret_cast<const float4*>(Bs);

    ull acc2[2][8];
    #pragma unroll
    for (int i = 0; i < 2; i++)
        #pragma unroll
        for (int j = 0; j < 8; j++) acc2[i][j] = 0ull;

    #pragma unroll 8
    for (int k = 0; k < 128; k++) {
        ulonglong2 a = Asu[k * (AS_W / 4) + tx];    // nodes 4tx..4tx+3
        float4 b0 = Bs4[k * 16 + ty * 2];
        float4 b1 = Bs4[k * 16 + ty * 2 + 1];
        ull av0 = a.x, av1 = a.y;
        float bv[8] = {b0.x, b0.y, b0.z, b0.w, b1.x, b1.y, b1.z, b1.w};
        #pragma unroll
        for (int j = 0; j < 8; j++) {
            ull bj = rep2(bv[j]);
            fma2(acc2[0][j], av0, bj);
            fma2(acc2[1][j], av1, bj);
        }
    }

    // ---- Epilogue ----
    float4* out4 = reinterpret_cast<float4*>(out);
    #pragma unroll
    for (int p = 0; p < 2; p++) {
        float oe[8], oo[8];
        #pragma unroll
        for (int j = 0; j < 8; j++) {
            float2 v = unpack2(acc2[p][j]);
            float bb = bs[ty * 8 + j];
            float e = v.x + bb, o = v.y + bb;
            if (RELU) { e = fmaxf(e, 0.0f); o = fmaxf(o, 0.0f); }
            oe[j] = e; oo[j] = o;
        }
        int node_e = base + tx * 4 + 2 * p;
        if (node_e < N_NODES) {
            out4[(size_t)node_e * 16 + ty * 2]     = make_float4(oe[0], oe[1], oe[2], oe[3]);
            out4[(size_t)node_e * 16 + ty * 2 + 1] = make_float4(oe[4], oe[5], oe[6], oe[7]);
        }
        if (node_e + 1 < N_NODES) {
            out4[(size_t)(node_e + 1) * 16 + ty * 2]     = make_float4(oo[0], oo[1], oo[2], oo[3]);
            out4[(size_t)(node_e + 1) * 16 + ty * 2 + 1] = make_float4(oo[4], oo[5], oo[6], oo[7]);
        }
    }
}

extern "C" void kernel_launch(void* const* d_in, const int* in_sizes, int n_in,
                              void* d_out, int out_size)
{
    const float* x  = (const float*)d_in[0];
    const int*   ei = (const int*)  d_in[1];
    const float* W0 = (const float*)d_in[2];
    const float* b0 = (const float*)d_in[3];
    const float* W1 = (const float*)d_in[4];
    const float* b1 = (const float*)d_in[5];
    float* out = (float*)d_out;

    void *cnt_ptr = nullptr, *h1_ptr = nullptr;
    cudaGetSymbolAddress(&cnt_ptr, g_cnt);
    cudaGetSymbolAddress(&h1_ptr,  g_h1);
    float* h1 = (float*)h1_ptr;

    const int smem_bytes = (128 * AS_W + 128 * 64) * sizeof(float);  // 100352B
    cudaFuncSetAttribute(fused_layer_kernel<true>,
                         cudaFuncAttributeMaxDynamicSharedMemorySize, smem_bytes);
    cudaFuncSetAttribute(fused_layer_kernel<false>,
                         cudaFuncAttributeMaxDynamicSharedMemorySize, smem_bytes);

    const int build_blocks = (N_EDGES / 4 + 255) / 256;
    const int layer_blocks = (N_NODES + NODES_PER_BLK - 1) / NODES_PER_BLK;  // 782

    cudaMemsetAsync(cnt_ptr, 0, N_NODES * sizeof(int));
    build_adj_kernel<<<build_blocks, 256>>>(ei);

    fused_layer_kernel<true ><<<layer_blocks, 256, smem_bytes>>>(x,  W0, b0, h1);
    fused_layer_kernel<false><<<layer_blocks, 256, smem_bytes>>>(h1, W1, b1, out);
}

// round 11
// speedup vs baseline: 1.6729x; 1.6729x over previous
#include <cuda_runtime.h>
#include <cuda_bf16.h>
#include <cstdint>

#define N_NODES 100000
#define N_EDGES 2000000
#define DIM 64
#define CAP 96   // max in-degree capacity (deg ~ Poisson(20); P(max>96) ~ 0)

// ---- smem layout for the mma transform (bf16 tiles, 136-elem row stride) ----
#define AST 136                              // row stride in bf16 elems (272B)
#define SOFF_BIAS 0                          // 64 f32
#define SOFF_AHI  256                        // 128 x 136 bf16 = 34816 B
#define SOFF_ALO  (256 + 34816)
#define SOFF_BHI  (256 + 2 * 34816)          // 64 x 136 bf16 = 17408 B
#define SOFF_BLO  (256 + 2 * 34816 + 17408)
#define SMEM_XF_TOTAL (256 + 2 * 34816 + 2 * 17408)   // 104704 B (2 blocks/SM)

// Scratch (no cudaMalloc allowed)
__device__ int g_cnt[N_NODES];
__device__ __align__(16) int g_adj[(size_t)N_NODES * CAP];       // 38.4 MB
__device__ __align__(16) float g_agg[(size_t)N_NODES * DIM];     // mean (pre-scaled)
__device__ __align__(16) float g_h1[(size_t)N_NODES * DIM];
// Pre-split W^T tiles [n=64][k=128] bf16: [L0hi, L0lo, L1hi, L1lo]
__device__ __align__(16) unsigned short g_wt[4][64 * 128];

__device__ __forceinline__ uint32_t smem_u32(const void* p) {
    uint32_t a;
    asm("{ .reg .u64 t; cvta.to.shared.u64 t, %1; cvt.u32.u64 %0, t; }"
        : "=r"(a) : "l"(p));
    return a;
}

// ---------------------------------------------------------------------------
// Build per-destination adjacency buckets (1 edge/thread: max atomic MLP).
// ---------------------------------------------------------------------------
__global__ void __launch_bounds__(256)
build_adj_kernel(const int* __restrict__ ei)
{
    unsigned e = blockIdx.x * blockDim.x + threadIdx.x;
    if (e >= N_EDGES) return;
    int src = ei[e];
    int dst = ei[N_EDGES + e];
    int slot = atomicAdd(&g_cnt[dst], 1);
    if (slot < CAP) g_adj[(size_t)dst * CAP + slot] = src;
}

// ---------------------------------------------------------------------------
// Pre-split W into hi/lo bf16 W^T tiles: g_wt[..][n*128+k] = bf16(W[k][n]).
// ---------------------------------------------------------------------------
__global__ void wprep_kernel(const float* __restrict__ W0, const float* __restrict__ W1)
{
    int layer = blockIdx.x;
    const float* W = layer ? W1 : W0;
    for (int idx = threadIdx.x; idx < 64 * 128; idx += blockDim.x) {
        int n = idx >> 7, k = idx & 127;
        float w = W[k * 64 + n];
        __nv_bfloat16 hi = __float2bfloat16(w);
        __nv_bfloat16 lo = __float2bfloat16(w - __bfloat162float(hi));
        g_wt[layer * 2 + 0][idx] = *reinterpret_cast<unsigned short*>(&hi);
        g_wt[layer * 2 + 1][idx] = *reinterpret_cast<unsigned short*>(&lo);
    }
}

// ---------------------------------------------------------------------------
// Gather + mean into g_agg (R7 version: at the L2 structural floor).
// ---------------------------------------------------------------------------
__global__ void __launch_bounds__(256)
gather_kernel(const float* __restrict__ h)
{
    const int lane = threadIdx.x & 31;
    const int half = lane >> 4;
    const int sub  = lane & 15;
    const int warp = threadIdx.x >> 5;
    const int node = blockIdx.x * 8 + warp;   // grid exact (100000/8)

    const int deg = g_cnt[node];
    const int cnt = min(deg, CAP);
    const int* __restrict__ adj = g_adj + node * CAP;
    const float4* __restrict__ h4 = reinterpret_cast<const float4*>(h);

    float4 acc = make_float4(0.f, 0.f, 0.f, 0.f);
    int j = 0;
    for (; j + 8 <= cnt; j += 8) {
        int4 ia = *reinterpret_cast<const int4*>(adj + j);
        int4 ib = *reinterpret_cast<const int4*>(adj + j + 4);
        int s0 = half ? ia.y : ia.x;
        int s1 = half ? ia.w : ia.z;
        int s2 = half ? ib.y : ib.x;
        int s3 = half ? ib.w : ib.z;
        float4 v0 = h4[s0 * 16 + sub];
        float4 v1 = h4[s1 * 16 + sub];
        float4 v2 = h4[s2 * 16 + sub];
        float4 v3 = h4[s3 * 16 + sub];
        acc.x += (v0.x + v1.x) + (v2.x + v3.x);
        acc.y += (v0.y + v1.y) + (v2.y + v3.y);
        acc.z += (v0.z + v1.z) + (v2.z + v3.z);
        acc.w += (v0.w + v1.w) + (v2.w + v3.w);
    }
    for (; j + 2 <= cnt; j += 2) {
        int2 ia = *reinterpret_cast<const int2*>(adj + j);
        int s = half ? ia.y : ia.x;
        float4 v = h4[s * 16 + sub];
        acc.x += v.x; acc.y += v.y; acc.z += v.z; acc.w += v.w;
    }
    if (j < cnt && half == 0) {
        float4 v = h4[adj[j] * 16 + sub];
        acc.x += v.x; acc.y += v.y; acc.z += v.z; acc.w += v.w;
    }

    acc.x += __shfl_xor_sync(0xffffffffu, acc.x, 16);
    acc.y += __shfl_xor_sync(0xffffffffu, acc.y, 16);
    acc.z += __shfl_xor_sync(0xffffffffu, acc.z, 16);
    acc.w += __shfl_xor_sync(0xffffffffu, acc.w, 16);

    if (half == 0) {
        float inv = 1.0f / fmaxf((float)deg, 1.0f);
        acc.x *= inv; acc.y *= inv; acc.z *= inv; acc.w *= inv;
        reinterpret_cast<float4*>(g_agg)[node * 16 + sub] = acc;
    }
}

// Split 4 floats into hi/lo bf16x2 pairs (two uint32 each).
__device__ __forceinline__ void split4(float4 v, uint2& hi, uint2& lo)
{
    __nv_bfloat162 h01 = __float22bfloat162_rn(make_float2(v.x, v.y));
    __nv_bfloat162 h23 = __float22bfloat162_rn(make_float2(v.z, v.w));
    __nv_bfloat162 l01 = __float22bfloat162_rn(make_float2(
        v.x - __bfloat162float(h01.x), v.y - __bfloat162float(h01.y)));
    __nv_bfloat162 l23 = __float22bfloat162_rn(make_float2(
        v.z - __bfloat162float(h23.x), v.w - __bfloat162float(h23.y)));
    hi.x = *reinterpret_cast<uint32_t*>(&h01);
    hi.y = *reinterpret_cast<uint32_t*>(&h23);
    lo.x = *reinterpret_cast<uint32_t*>(&l01);
    lo.y = *reinterpret_cast<uint32_t*>(&l23);
}

__device__ __forceinline__ void ldsm4(uint32_t& r0, uint32_t& r1, uint32_t& r2,
                                      uint32_t& r3, uint32_t addr)
{
    asm volatile("ldmatrix.sync.aligned.m8n8.x4.shared.b16 {%0,%1,%2,%3}, [%4];"
                 : "=r"(r0), "=r"(r1), "=r"(r2), "=r"(r3) : "r"(addr));
}

__device__ __forceinline__ void mma16816(float* c, uint32_t a0, uint32_t a1,
                                         uint32_t a2, uint32_t a3,
                                         uint32_t b0, uint32_t b1)
{
    asm volatile(
        "mma.sync.aligned.m16n8k16.row.col.f32.bf16.bf16.f32 "
        "{%0,%1,%2,%3}, {%4,%5,%6,%7}, {%8,%9}, {%0,%1,%2,%3};"
        : "+f"(c[0]), "+f"(c[1]), "+f"(c[2]), "+f"(c[3])
        : "r"(a0), "r"(a1), "r"(a2), "r"(a3), "r"(b0), "r"(b1));
}

// ---------------------------------------------------------------------------
// Transform via warp-level bf16 mma.sync, 3-pass split (fp32-class accuracy):
// D = Ahi@Bhi + Alo@Bhi + Ahi@Blo. Block: 128 nodes x 64 cols, K=128.
// 8 warps, each computes a 16-node x 64-col stripe.
// ---------------------------------------------------------------------------
template <bool RELU>
__global__ void __launch_bounds__(256)
xform_mma_kernel(const float* __restrict__ h,
                 const unsigned short* __restrict__ wt_hi,
                 const unsigned short* __restrict__ wt_lo,
                 const float* __restrict__ b,
                 float* __restrict__ out)
{
    extern __shared__ __align__(16) char smem[];
    float* bias = reinterpret_cast<float*>(smem);
    char* Ahi = smem + SOFF_AHI;
    char* Alo = smem + SOFF_ALO;
    char* Bhi = smem + SOFF_BHI;
    char* Blo = smem + SOFF_BLO;

    const int tid  = threadIdx.x;
    const int lane = tid & 31;
    const int warp = tid >> 5;
    const int base = blockIdx.x * 128;

    if (tid < 64) bias[tid] = b[tid];

    // Stage B tiles: rows of 128 bf16 (256B) -> stride-272B smem rows.
    {
        int row = tid >> 2, q = tid & 3;      // 4 threads per row, 4 float4 each
        const float4* sh = reinterpret_cast<const float4*>(wt_hi) + row * 16 + q * 4;
        const float4* sl = reinterpret_cast<const float4*>(wt_lo) + row * 16 + q * 4;
        float4* dh = reinterpret_cast<float4*>(Bhi + row * (AST * 2)) + q * 4;
        float4* dl = reinterpret_cast<float4*>(Blo + row * (AST * 2)) + q * 4;
        #pragma unroll
        for (int i = 0; i < 4; i++) { dh[i] = sh[i]; dl[i] = sl[i]; }
    }

    // Stage A: thread t -> node_l = t>>1, half = t&1 (h vs agg 64-feature half)
    {
        int node_l = tid >> 1;
        int half = tid & 1;
        int node = base + node_l;
        if (node >= N_NODES) node = N_NODES - 1;   // clamp; stores guarded later
        const float4* src = reinterpret_cast<const float4*>(half ? g_agg : h);
        char* rh = Ahi + node_l * (AST * 2) + half * 128;
        char* rl = Alo + node_l * (AST * 2) + half * 128;
        #pragma unroll
        for (int c = 0; c < 16; c++) {
            uint2 hi, lo;
            split4(src[(size_t)node * 16 + c], hi, lo);
            *reinterpret_cast<uint2*>(rh + c * 8) = hi;
            *reinterpret_cast<uint2*>(rl + c * 8) = lo;
        }
    }
    __syncthreads();

    // ---- MMA mainloop ----
    const int m0 = warp * 16;
    float acc[8][4];
    #pragma unroll
    for (int j = 0; j < 8; j++)
        #pragma unroll
        for (int q = 0; q < 4; q++) acc[j][q] = 0.0f;

    // ldmatrix lane address components (element offsets within a row handled in bytes)
    const uint32_t a_row = (uint32_t)(m0 + (lane & 15)) * (AST * 2) + ((lane >> 4) << 4);
    const uint32_t b_row = (uint32_t)((lane & 7) + ((lane >> 4) << 3)) * (AST * 2)
                           + (((lane >> 3) & 1) << 4);

    #pragma unroll
    for (int p = 0; p < 3; p++) {
        const uint32_t Abase = smem_u32(p == 1 ? Alo : Ahi) + a_row;
        const uint32_t Bbase = smem_u32(p == 2 ? Blo : Bhi) + b_row;
        #pragma unroll
        for (int kk = 0; kk < 8; kk++) {
            uint32_t a0, a1, a2, a3;
            ldsm4(a0, a1, a2, a3, Abase + kk * 32);
            #pragma unroll
            for (int jj = 0; jj < 4; jj++) {
                uint32_t b0, b1, b2, b3;
                ldsm4(b0, b1, b2, b3, Bbase + jj * 16 * (AST * 2) + kk * 32);
                mma16816(acc[2 * jj],     a0, a1, a2, a3, b0, b1);
                mma16816(acc[2 * jj + 1], a0, a1, a2, a3, b2, b3);
            }
        }
    }

    // ---- Epilogue: bias (+ReLU), float2 stores ----
    const int r0 = m0 + (lane >> 2);
    const int c0 = 2 * (lane & 3);
    const int node0 = base + r0;
    const int node1 = node0 + 8;
    #pragma unroll
    for (int j = 0; j < 8; j++) {
        int col = j * 8 + c0;
        float bb0 = bias[col], bb1 = bias[col + 1];
        if (node0 < N_NODES) {
            float x0 = acc[j][0] + bb0, x1 = acc[j][1] + bb1;
            if (RELU) { x0 = fmaxf(x0, 0.f); x1 = fmaxf(x1, 0.f); }
            *reinterpret_cast<float2*>(out + (size_t)node0 * DIM + col) = make_float2(x0, x1);
        }
        if (node1 < N_NODES) {
            float x2 = acc[j][2] + bb0, x3 = acc[j][3] + bb1;
            if (RELU) { x2 = fmaxf(x2, 0.f); x3 = fmaxf(x3, 0.f); }
            *reinterpret_cast<float2*>(out + (size_t)node1 * DIM + col) = make_float2(x2, x3);
        }
    }
}

extern "C" void kernel_launch(void* const* d_in, const int* in_sizes, int n_in,
                              void* d_out, int out_size)
{
    const float* x  = (const float*)d_in[0];
    const int*   ei = (const int*)  d_in[1];
    const float* W0 = (const float*)d_in[2];
    const float* b0 = (const float*)d_in[3];
    const float* W1 = (const float*)d_in[4];
    const float* b1 = (const float*)d_in[5];
    float* out = (float*)d_out;

    void *cnt_ptr = nullptr, *h1_ptr = nullptr, *wt_ptr = nullptr;
    cudaGetSymbolAddress(&cnt_ptr, g_cnt);
    cudaGetSymbolAddress(&h1_ptr,  g_h1);
    cudaGetSymbolAddress(&wt_ptr,  g_wt);
    float* h1 = (float*)h1_ptr;
    const unsigned short* wt = (const unsigned short*)wt_ptr;

    cudaFuncSetAttribute(xform_mma_kernel<true>,
                         cudaFuncAttributeMaxDynamicSharedMemorySize, SMEM_XF_TOTAL);
    cudaFuncSetAttribute(xform_mma_kernel<false>,
                         cudaFuncAttributeMaxDynamicSharedMemorySize, SMEM_XF_TOTAL);

    const int build_blocks  = (N_EDGES + 255) / 256;
    const int gather_blocks = N_NODES / 8;                     // exact
    const int xform_blocks  = (N_NODES + 127) / 128;           // 782

    cudaMemsetAsync(cnt_ptr, 0, N_NODES * sizeof(int));
    build_adj_kernel<<<build_blocks, 256>>>(ei);
    wprep_kernel<<<2, 256>>>(W0, W1);

    // ---- Layer 0 ----
    gather_kernel<<<gather_blocks, 256>>>(x);
    xform_mma_kernel<true><<<xform_blocks, 256, SMEM_XF_TOTAL>>>(
        x, wt + 0 * 8192, wt + 1 * 8192, b0, h1);

    // ---- Layer 1 ----
    gather_kernel<<<gather_blocks, 256>>>(h1);
    xform_mma_kernel<false><<<xform_blocks, 256, SMEM_XF_TOTAL>>>(
        h1, wt + 2 * 8192, wt + 3 * 8192, b1, out);
}

// round 12
// speedup vs baseline: 1.6912x; 1.0109x over previous
#include <cuda_runtime.h>
#include <cuda_bf16.h>
#include <cstdint>

#define N_NODES 100000
#define N_EDGES 2000000
#define DIM 64
#define CAP 96   // max in-degree capacity (deg ~ Poisson(20); P(max>96) ~ 0)

// ---- smem layout for the mma transform (bf16 tiles, 136-elem row stride) ----
#define AST 136                              // row stride in bf16 elems (272B)
#define SOFF_BIAS 0                          // 64 f32
#define SOFF_AHI  256                        // 128 x 136 bf16 = 34816 B
#define SOFF_ALO  (256 + 34816)
#define SOFF_BHI  (256 + 2 * 34816)          // 64 x 136 bf16 = 17408 B
#define SOFF_BLO  (256 + 2 * 34816 + 17408)
#define SMEM_XF_TOTAL (256 + 2 * 34816 + 2 * 17408)   // 104704 B (2 blocks/SM)

// Scratch (no cudaMalloc allowed)
__device__ int g_cnt[N_NODES];
__device__ __align__(16) int g_adj[(size_t)N_NODES * CAP];       // 38.4 MB
__device__ __align__(16) float g_agg[(size_t)N_NODES * DIM];     // mean (pre-scaled)
__device__ __align__(16) float g_h1[(size_t)N_NODES * DIM];
// Pre-split W^T tiles [n=64][k=128] bf16: [L0hi, L0lo, L1hi, L1lo]
__device__ __align__(16) unsigned short g_wt[4][64 * 128];

__device__ __forceinline__ uint32_t smem_u32(const void* p) {
    uint32_t a;
    asm("{ .reg .u64 t; cvta.to.shared.u64 t, %1; cvt.u32.u64 %0, t; }"
        : "=r"(a) : "l"(p));
    return a;
}

// ---------------------------------------------------------------------------
// Build per-destination adjacency buckets (1 edge/thread: max atomic MLP).
// ---------------------------------------------------------------------------
__global__ void __launch_bounds__(256)
build_adj_kernel(const int* __restrict__ ei)
{
    unsigned e = blockIdx.x * blockDim.x + threadIdx.x;
    if (e >= N_EDGES) return;
    int src = ei[e];
    int dst = ei[N_EDGES + e];
    int slot = atomicAdd(&g_cnt[dst], 1);
    if (slot < CAP) g_adj[(size_t)dst * CAP + slot] = src;
}

// ---------------------------------------------------------------------------
// Pre-split W into hi/lo bf16 W^T tiles: g_wt[..][n*128+k] = bf16(W[k][n]).
// ---------------------------------------------------------------------------
__global__ void wprep_kernel(const float* __restrict__ W0, const float* __restrict__ W1)
{
    int layer = blockIdx.x;
    const float* W = layer ? W1 : W0;
    for (int idx = threadIdx.x; idx < 64 * 128; idx += blockDim.x) {
        int n = idx >> 7, k = idx & 127;
        float w = W[k * 64 + n];
        __nv_bfloat16 hi = __float2bfloat16(w);
        __nv_bfloat16 lo = __float2bfloat16(w - __bfloat162float(hi));
        g_wt[layer * 2 + 0][idx] = *reinterpret_cast<unsigned short*>(&hi);
        g_wt[layer * 2 + 1][idx] = *reinterpret_cast<unsigned short*>(&lo);
    }
}

// ---------------------------------------------------------------------------
// Gather + mean into g_agg (R7 version: at the L2 structural floor).
// ---------------------------------------------------------------------------
__global__ void __launch_bounds__(256)
gather_kernel(const float* __restrict__ h)
{
    const int lane = threadIdx.x & 31;
    const int half = lane >> 4;
    const int sub  = lane & 15;
    const int warp = threadIdx.x >> 5;
    const int node = blockIdx.x * 8 + warp;   // grid exact (100000/8)

    const int deg = g_cnt[node];
    const int cnt = min(deg, CAP);
    const int* __restrict__ adj = g_adj + node * CAP;
    const float4* __restrict__ h4 = reinterpret_cast<const float4*>(h);

    float4 acc = make_float4(0.f, 0.f, 0.f, 0.f);
    int j = 0;
    for (; j + 8 <= cnt; j += 8) {
        int4 ia = *reinterpret_cast<const int4*>(adj + j);
        int4 ib = *reinterpret_cast<const int4*>(adj + j + 4);
        int s0 = half ? ia.y : ia.x;
        int s1 = half ? ia.w : ia.z;
        int s2 = half ? ib.y : ib.x;
        int s3 = half ? ib.w : ib.z;
        float4 v0 = h4[s0 * 16 + sub];
        float4 v1 = h4[s1 * 16 + sub];
        float4 v2 = h4[s2 * 16 + sub];
        float4 v3 = h4[s3 * 16 + sub];
        acc.x += (v0.x + v1.x) + (v2.x + v3.x);
        acc.y += (v0.y + v1.y) + (v2.y + v3.y);
        acc.z += (v0.z + v1.z) + (v2.z + v3.z);
        acc.w += (v0.w + v1.w) + (v2.w + v3.w);
    }
    for (; j + 2 <= cnt; j += 2) {
        int2 ia = *reinterpret_cast<const int2*>(adj + j);
        int s = half ? ia.y : ia.x;
        float4 v = h4[s * 16 + sub];
        acc.x += v.x; acc.y += v.y; acc.z += v.z; acc.w += v.w;
    }
    if (j < cnt && half == 0) {
        float4 v = h4[adj[j] * 16 + sub];
        acc.x += v.x; acc.y += v.y; acc.z += v.z; acc.w += v.w;
    }

    acc.x += __shfl_xor_sync(0xffffffffu, acc.x, 16);
    acc.y += __shfl_xor_sync(0xffffffffu, acc.y, 16);
    acc.z += __shfl_xor_sync(0xffffffffu, acc.z, 16);
    acc.w += __shfl_xor_sync(0xffffffffu, acc.w, 16);

    if (half == 0) {
        float inv = 1.0f / fmaxf((float)deg, 1.0f);
        acc.x *= inv; acc.y *= inv; acc.z *= inv; acc.w *= inv;
        reinterpret_cast<float4*>(g_agg)[node * 16 + sub] = acc;
    }
}

// Split 4 floats into hi/lo bf16x2 pairs (two uint32 each).
__device__ __forceinline__ void split4(float4 v, uint2& hi, uint2& lo)
{
    __nv_bfloat162 h01 = __float22bfloat162_rn(make_float2(v.x, v.y));
    __nv_bfloat162 h23 = __float22bfloat162_rn(make_float2(v.z, v.w));
    __nv_bfloat162 l01 = __float22bfloat162_rn(make_float2(
        v.x - __bfloat162float(h01.x), v.y - __bfloat162float(h01.y)));
    __nv_bfloat162 l23 = __float22bfloat162_rn(make_float2(
        v.z - __bfloat162float(h23.x), v.w - __bfloat162float(h23.y)));
    hi.x = *reinterpret_cast<uint32_t*>(&h01);
    hi.y = *reinterpret_cast<uint32_t*>(&h23);
    lo.x = *reinterpret_cast<uint32_t*>(&l01);
    lo.y = *reinterpret_cast<uint32_t*>(&l23);
}

__device__ __forceinline__ void ldsm4(uint32_t& r0, uint32_t& r1, uint32_t& r2,
                                      uint32_t& r3, uint32_t addr)
{
    asm volatile("ldmatrix.sync.aligned.m8n8.x4.shared.b16 {%0,%1,%2,%3}, [%4];"
                 : "=r"(r0), "=r"(r1), "=r"(r2), "=r"(r3) : "r"(addr));
}

__device__ __forceinline__ void mma16816(float* c, uint32_t a0, uint32_t a1,
                                         uint32_t a2, uint32_t a3,
                                         uint32_t b0, uint32_t b1)
{
    asm volatile(
        "mma.sync.aligned.m16n8k16.row.col.f32.bf16.bf16.f32 "
        "{%0,%1,%2,%3}, {%4,%5,%6,%7}, {%8,%9}, {%0,%1,%2,%3};"
        : "+f"(c[0]), "+f"(c[1]), "+f"(c[2]), "+f"(c[3])
        : "r"(a0), "r"(a1), "r"(a2), "r"(a3), "r"(b0), "r"(b1));
}

// ---------------------------------------------------------------------------
// Transform via warp-level bf16 mma.sync, split-bf16 in a SINGLE fused k-loop:
// per k-chunk, load Ahi/Alo once and Bhi/Blo once, then issue
// Ahi@Bhi + Alo@Bhi + Ahi@Blo from the same fragments (fp32-class accuracy).
// Block: 128 nodes x 64 cols, K=128; 8 warps, 16-node stripe each.
// 2 blocks/SM (regs capped at 128) to hide LDSM/LDS latency.
// ---------------------------------------------------------------------------
template <bool RELU>
__global__ void __launch_bounds__(256, 2)
xform_mma_kernel(const float* __restrict__ h,
                 const unsigned short* __restrict__ wt_hi,
                 const unsigned short* __restrict__ wt_lo,
                 const float* __restrict__ b,
                 float* __restrict__ out)
{
    extern __shared__ __align__(16) char smem[];
    float* bias = reinterpret_cast<float*>(smem);
    char* Ahi = smem + SOFF_AHI;
    char* Alo = smem + SOFF_ALO;
    char* Bhi = smem + SOFF_BHI;
    char* Blo = smem + SOFF_BLO;

    const int tid  = threadIdx.x;
    const int lane = tid & 31;
    const int warp = tid >> 5;
    const int base = blockIdx.x * 128;

    if (tid < 64) bias[tid] = b[tid];

    // Stage B tiles: rows of 128 bf16 (256B) -> stride-272B smem rows.
    {
        int row = tid >> 2, q = tid & 3;      // 4 threads per row, 4 float4 each
        const float4* sh = reinterpret_cast<const float4*>(wt_hi) + row * 16 + q * 4;
        const float4* sl = reinterpret_cast<const float4*>(wt_lo) + row * 16 + q * 4;
        float4* dh = reinterpret_cast<float4*>(Bhi + row * (AST * 2)) + q * 4;
        float4* dl = reinterpret_cast<float4*>(Blo + row * (AST * 2)) + q * 4;
        #pragma unroll
        for (int i = 0; i < 4; i++) { dh[i] = sh[i]; dl[i] = sl[i]; }
    }

    // Stage A: thread t -> node_l = t>>1, half = t&1 (h vs agg 64-feature half)
    {
        int node_l = tid >> 1;
        int half = tid & 1;
        int node = base + node_l;
        if (node >= N_NODES) node = N_NODES - 1;   // clamp; stores guarded later
        const float4* src = reinterpret_cast<const float4*>(half ? g_agg : h);
        char* rh = Ahi + node_l * (AST * 2) + half * 128;
        char* rl = Alo + node_l * (AST * 2) + half * 128;
        #pragma unroll
        for (int c = 0; c < 16; c++) {
            uint2 hi, lo;
            split4(src[(size_t)node * 16 + c], hi, lo);
            *reinterpret_cast<uint2*>(rh + c * 8) = hi;
            *reinterpret_cast<uint2*>(rl + c * 8) = lo;
        }
    }
    __syncthreads();

    // ---- Fused MMA mainloop ----
    const int m0 = warp * 16;
    float acc[8][4];
    #pragma unroll
    for (int j = 0; j < 8; j++)
        #pragma unroll
        for (int q = 0; q < 4; q++) acc[j][q] = 0.0f;

    const uint32_t a_row = (uint32_t)(m0 + (lane & 15)) * (AST * 2) + ((lane >> 4) << 4);
    const uint32_t b_row = (uint32_t)((lane & 7) + ((lane >> 4) << 3)) * (AST * 2)
                           + (((lane >> 3) & 1) << 4);
    const uint32_t AhiB = smem_u32(Ahi) + a_row;
    const uint32_t AloB = smem_u32(Alo) + a_row;
    const uint32_t BhiB = smem_u32(Bhi) + b_row;
    const uint32_t BloB = smem_u32(Blo) + b_row;

    #pragma unroll
    for (int kk = 0; kk < 8; kk++) {
        uint32_t ah0, ah1, ah2, ah3, al0, al1, al2, al3;
        ldsm4(ah0, ah1, ah2, ah3, AhiB + kk * 32);
        ldsm4(al0, al1, al2, al3, AloB + kk * 32);
        #pragma unroll
        for (int jj = 0; jj < 4; jj++) {
            uint32_t bh0, bh1, bh2, bh3, bl0, bl1, bl2, bl3;
            ldsm4(bh0, bh1, bh2, bh3, BhiB + jj * 16 * (AST * 2) + kk * 32);
            ldsm4(bl0, bl1, bl2, bl3, BloB + jj * 16 * (AST * 2) + kk * 32);
            mma16816(acc[2 * jj],     ah0, ah1, ah2, ah3, bh0, bh1);
            mma16816(acc[2 * jj + 1], ah0, ah1, ah2, ah3, bh2, bh3);
            mma16816(acc[2 * jj],     al0, al1, al2, al3, bh0, bh1);
            mma16816(acc[2 * jj + 1], al0, al1, al2, al3, bh2, bh3);
            mma16816(acc[2 * jj],     ah0, ah1, ah2, ah3, bl0, bl1);
            mma16816(acc[2 * jj + 1], ah0, ah1, ah2, ah3, bl2, bl3);
        }
    }

    // ---- Epilogue: bias (+ReLU), float2 stores ----
    const int r0 = m0 + (lane >> 2);
    const int c0 = 2 * (lane & 3);
    const int node0 = base + r0;
    const int node1 = node0 + 8;
    #pragma unroll
    for (int j = 0; j < 8; j++) {
        int col = j * 8 + c0;
        float bb0 = bias[col], bb1 = bias[col + 1];
        if (node0 < N_NODES) {
            float x0 = acc[j][0] + bb0, x1 = acc[j][1] + bb1;
            if (RELU) { x0 = fmaxf(x0, 0.f); x1 = fmaxf(x1, 0.f); }
            *reinterpret_cast<float2*>(out + (size_t)node0 * DIM + col) = make_float2(x0, x1);
        }
        if (node1 < N_NODES) {
            float x2 = acc[j][2] + bb0, x3 = acc[j][3] + bb1;
            if (RELU) { x2 = fmaxf(x2, 0.f); x3 = fmaxf(x3, 0.f); }
            *reinterpret_cast<float2*>(out + (size_t)node1 * DIM + col) = make_float2(x2, x3);
        }
    }
}

extern "C" void kernel_launch(void* const* d_in, const int* in_sizes, int n_in,
                              void* d_out, int out_size)
{
    const float* x  = (const float*)d_in[0];
    const int*   ei = (const int*)  d_in[1];
    const float* W0 = (const float*)d_in[2];
    const float* b0 = (const float*)d_in[3];
    const float* W1 = (const float*)d_in[4];
    const float* b1 = (const float*)d_in[5];
    float* out = (float*)d_out;

    void *cnt_ptr = nullptr, *h1_ptr = nullptr, *wt_ptr = nullptr;
    cudaGetSymbolAddress(&cnt_ptr, g_cnt);
    cudaGetSymbolAddress(&h1_ptr,  g_h1);
    cudaGetSymbolAddress(&wt_ptr,  g_wt);
    float* h1 = (float*)h1_ptr;
    const unsigned short* wt = (const unsigned short*)wt_ptr;

    cudaFuncSetAttribute(xform_mma_kernel<true>,
                         cudaFuncAttributeMaxDynamicSharedMemorySize, SMEM_XF_TOTAL);
    cudaFuncSetAttribute(xform_mma_kernel<false>,
                         cudaFuncAttributeMaxDynamicSharedMemorySize, SMEM_XF_TOTAL);

    const int build_blocks  = (N_EDGES + 255) / 256;
    const int gather_blocks = N_NODES / 8;                     // exact
    const int xform_blocks  = (N_NODES + 127) / 128;           // 782

    cudaMemsetAsync(cnt_ptr, 0, N_NODES * sizeof(int));
    build_adj_kernel<<<build_blocks, 256>>>(ei);
    wprep_kernel<<<2, 256>>>(W0, W1);

    // ---- Layer 0 ----
    gather_kernel<<<gather_blocks, 256>>>(x);
    xform_mma_kernel<true><<<xform_blocks, 256, SMEM_XF_TOTAL>>>(
        x, wt + 0 * 8192, wt + 1 * 8192, b0, h1);

    // ---- Layer 1 ----
    gather_kernel<<<gather_blocks, 256>>>(h1);
    xform_mma_kernel<false><<<xform_blocks, 256, SMEM_XF_TOTAL>>>(
        h1, wt + 2 * 8192, wt + 3 * 8192, b1, out);
}

// round 13
// speedup vs baseline: 1.9187x; 1.1345x over previous
#include <cuda_runtime.h>
#include <cuda_bf16.h>
#include <cstdint>

#define N_NODES 100000
#define N_EDGES 2000000
#define DIM 64
#define CAP 96   // max in-degree capacity (deg ~ Poisson(20); P(max>96) ~ 0)

// ---- smem layout for the mma transform (bf16 tiles, 136-elem row stride) ----
#define AST 136                              // row stride in bf16 elems (272B)
#define SOFF_BIAS 0                          // 64 f32
#define SOFF_AHI  256                        // 128 x 136 bf16 = 34816 B
#define SOFF_ALO  (256 + 34816)
#define SOFF_BHI  (256 + 2 * 34816)          // 64 x 136 bf16 = 17408 B
#define SOFF_BLO  (256 + 2 * 34816 + 17408)
#define SMEM_XF_TOTAL (256 + 2 * 34816 + 2 * 17408)   // 104704 B (2 blocks/SM)
// Epilogue f32 tile reuses the Ahi/Alo region: 128 rows x 72-word stride (288B)
#define EPI_STRIDE 72

// Scratch (no cudaMalloc allowed)
__device__ int g_cnt[N_NODES];
__device__ __align__(16) int g_adj[(size_t)N_NODES * CAP];       // 38.4 MB
__device__ __align__(16) float g_agg[(size_t)N_NODES * DIM];     // mean (pre-scaled)
__device__ __align__(16) float g_h1[(size_t)N_NODES * DIM];
// Pre-split W^T tiles [n=64][k=128] bf16: [L0hi, L0lo, L1hi, L1lo]
__device__ __align__(16) unsigned short g_wt[4][64 * 128];

__device__ __forceinline__ uint32_t smem_u32(const void* p) {
    uint32_t a;
    asm("{ .reg .u64 t; cvta.to.shared.u64 t, %1; cvt.u32.u64 %0, t; }"
        : "=r"(a) : "l"(p));
    return a;
}

// ---------------------------------------------------------------------------
// Build per-destination adjacency buckets (1 edge/thread: max atomic MLP).
// ---------------------------------------------------------------------------
__global__ void __launch_bounds__(256)
build_adj_kernel(const int* __restrict__ ei)
{
    unsigned e = blockIdx.x * blockDim.x + threadIdx.x;
    if (e >= N_EDGES) return;
    int src = ei[e];
    int dst = ei[N_EDGES + e];
    int slot = atomicAdd(&g_cnt[dst], 1);
    if (slot < CAP) g_adj[(size_t)dst * CAP + slot] = src;
}

// ---------------------------------------------------------------------------
// Pre-split W into hi/lo bf16 W^T tiles: g_wt[..][n*128+k] = bf16(W[k][n]).
// ---------------------------------------------------------------------------
__global__ void wprep_kernel(const float* __restrict__ W0, const float* __restrict__ W1)
{
    int layer = blockIdx.x;
    const float* W = layer ? W1 : W0;
    for (int idx = threadIdx.x; idx < 64 * 128; idx += blockDim.x) {
        int n = idx >> 7, k = idx & 127;
        float w = W[k * 64 + n];
        __nv_bfloat16 hi = __float2bfloat16(w);
        __nv_bfloat16 lo = __float2bfloat16(w - __bfloat162float(hi));
        g_wt[layer * 2 + 0][idx] = *reinterpret_cast<unsigned short*>(&hi);
        g_wt[layer * 2 + 1][idx] = *reinterpret_cast<unsigned short*>(&lo);
    }
}

// ---------------------------------------------------------------------------
// Gather + mean into g_agg (R7 version: at the L2 structural floor).
// ---------------------------------------------------------------------------
__global__ void __launch_bounds__(256)
gather_kernel(const float* __restrict__ h)
{
    const int lane = threadIdx.x & 31;
    const int half = lane >> 4;
    const int sub  = lane & 15;
    const int warp = threadIdx.x >> 5;
    const int node = blockIdx.x * 8 + warp;   // grid exact (100000/8)

    const int deg = g_cnt[node];
    const int cnt = min(deg, CAP);
    const int* __restrict__ adj = g_adj + node * CAP;
    const float4* __restrict__ h4 = reinterpret_cast<const float4*>(h);

    float4 acc = make_float4(0.f, 0.f, 0.f, 0.f);
    int j = 0;
    for (; j + 8 <= cnt; j += 8) {
        int4 ia = *reinterpret_cast<const int4*>(adj + j);
        int4 ib = *reinterpret_cast<const int4*>(adj + j + 4);
        int s0 = half ? ia.y : ia.x;
        int s1 = half ? ia.w : ia.z;
        int s2 = half ? ib.y : ib.x;
        int s3 = half ? ib.w : ib.z;
        float4 v0 = h4[s0 * 16 + sub];
        float4 v1 = h4[s1 * 16 + sub];
        float4 v2 = h4[s2 * 16 + sub];
        float4 v3 = h4[s3 * 16 + sub];
        acc.x += (v0.x + v1.x) + (v2.x + v3.x);
        acc.y += (v0.y + v1.y) + (v2.y + v3.y);
        acc.z += (v0.z + v1.z) + (v2.z + v3.z);
        acc.w += (v0.w + v1.w) + (v2.w + v3.w);
    }
    for (; j + 2 <= cnt; j += 2) {
        int2 ia = *reinterpret_cast<const int2*>(adj + j);
        int s = half ? ia.y : ia.x;
        float4 v = h4[s * 16 + sub];
        acc.x += v.x; acc.y += v.y; acc.z += v.z; acc.w += v.w;
    }
    if (j < cnt && half == 0) {
        float4 v = h4[adj[j] * 16 + sub];
        acc.x += v.x; acc.y += v.y; acc.z += v.z; acc.w += v.w;
    }

    acc.x += __shfl_xor_sync(0xffffffffu, acc.x, 16);
    acc.y += __shfl_xor_sync(0xffffffffu, acc.y, 16);
    acc.z += __shfl_xor_sync(0xffffffffu, acc.z, 16);
    acc.w += __shfl_xor_sync(0xffffffffu, acc.w, 16);

    if (half == 0) {
        float inv = 1.0f / fmaxf((float)deg, 1.0f);
        acc.x *= inv; acc.y *= inv; acc.z *= inv; acc.w *= inv;
        reinterpret_cast<float4*>(g_agg)[node * 16 + sub] = acc;
    }
}

// Split 4 floats into hi/lo bf16x2 pairs (two uint32 each).
__device__ __forceinline__ void split4(float4 v, uint2& hi, uint2& lo)
{
    __nv_bfloat162 h01 = __float22bfloat162_rn(make_float2(v.x, v.y));
    __nv_bfloat162 h23 = __float22bfloat162_rn(make_float2(v.z, v.w));
    __nv_bfloat162 l01 = __float22bfloat162_rn(make_float2(
        v.x - __bfloat162float(h01.x), v.y - __bfloat162float(h01.y)));
    __nv_bfloat162 l23 = __float22bfloat162_rn(make_float2(
        v.z - __bfloat162float(h23.x), v.w - __bfloat162float(h23.y)));
    hi.x = *reinterpret_cast<uint32_t*>(&h01);
    hi.y = *reinterpret_cast<uint32_t*>(&h23);
    lo.x = *reinterpret_cast<uint32_t*>(&l01);
    lo.y = *reinterpret_cast<uint32_t*>(&l23);
}

__device__ __forceinline__ void ldsm4(uint32_t& r0, uint32_t& r1, uint32_t& r2,
                                      uint32_t& r3, uint32_t addr)
{
    asm volatile("ldmatrix.sync.aligned.m8n8.x4.shared.b16 {%0,%1,%2,%3}, [%4];"
                 : "=r"(r0), "=r"(r1), "=r"(r2), "=r"(r3) : "r"(addr));
}

__device__ __forceinline__ void mma16816(float* c, uint32_t a0, uint32_t a1,
                                         uint32_t a2, uint32_t a3,
                                         uint32_t b0, uint32_t b1)
{
    asm volatile(
        "mma.sync.aligned.m16n8k16.row.col.f32.bf16.bf16.f32 "
        "{%0,%1,%2,%3}, {%4,%5,%6,%7}, {%8,%9}, {%0,%1,%2,%3};"
        : "+f"(c[0]), "+f"(c[1]), "+f"(c[2]), "+f"(c[3])
        : "r"(a0), "r"(a1), "r"(a2), "r"(a3), "r"(b0), "r"(b1));
}

// ---------------------------------------------------------------------------
// Transform via warp-level bf16 mma.sync, split-bf16, single fused k-loop.
// Block: 128 nodes x 64 cols, K=128; 8 warps, 16-node stripe each.
// R13: fully coalesced A staging (half-warp per 256B row) + smem-routed
// coalesced epilogue. 2 blocks/SM.
// ---------------------------------------------------------------------------
template <bool RELU>
__global__ void __launch_bounds__(256, 2)
xform_mma_kernel(const float* __restrict__ h,
                 const unsigned short* __restrict__ wt_hi,
                 const unsigned short* __restrict__ wt_lo,
                 const float* __restrict__ b,
                 float* __restrict__ out)
{
    extern __shared__ __align__(16) char smem[];
    float* bias = reinterpret_cast<float*>(smem);
    char* Ahi = smem + SOFF_AHI;
    char* Alo = smem + SOFF_ALO;
    char* Bhi = smem + SOFF_BHI;
    char* Blo = smem + SOFF_BLO;
    float* epi = reinterpret_cast<float*>(smem + SOFF_AHI);   // reused post-loop

    const int tid  = threadIdx.x;
    const int lane = tid & 31;
    const int warp = tid >> 5;
    const int base = blockIdx.x * 128;

    if (tid < 64) bias[tid] = b[tid];

    // Stage B tiles: rows of 128 bf16 (256B) -> stride-272B smem rows.
    {
        int row = tid >> 2, q = tid & 3;      // 4 threads per row, 4 float4 each
        const float4* sh = reinterpret_cast<const float4*>(wt_hi) + row * 16 + q * 4;
        const float4* sl = reinterpret_cast<const float4*>(wt_lo) + row * 16 + q * 4;
        float4* dh = reinterpret_cast<float4*>(Bhi + row * (AST * 2)) + q * 4;
        float4* dl = reinterpret_cast<float4*>(Blo + row * (AST * 2)) + q * 4;
        #pragma unroll
        for (int i = 0; i < 4; i++) { dh[i] = sh[i]; dl[i] = sl[i]; }
    }

    // Stage A, coalesced: 256 virtual rows (0..127 = h, 128..255 = agg).
    // Per iteration a warp covers a consecutive row pair: lanes 0-15 row 2i,
    // lanes 16-31 row 2i+1, each lane one float4 -> 512B contiguous LDG.
    {
        const float4* __restrict__ h4 = reinterpret_cast<const float4*>(h);
        const float4* __restrict__ a4 = reinterpret_cast<const float4*>(g_agg);
        const int c = lane & 15;
        #pragma unroll
        for (int iter = 0; iter < 16; iter++) {
            int i = iter * 8 + warp;               // 0..127 row pair index
            int vr = 2 * i + (lane >> 4);          // virtual row 0..255
            int node_l = vr & 127;
            int node = base + node_l;
            if (node >= N_NODES) node = N_NODES - 1;   // clamp; stores guarded later
            const float4* src = (vr < 128) ? h4 : a4;
            float4 v = src[(size_t)node * 16 + c];
            uint2 hi, lo;
            split4(v, hi, lo);
            int off = node_l * (AST * 2) + ((vr >> 7) << 7) + c * 8;
            *reinterpret_cast<uint2*>(Ahi + off) = hi;
            *reinterpret_cast<uint2*>(Alo + off) = lo;
        }
    }
    __syncthreads();

    // ---- Fused MMA mainloop ----
    const int m0 = warp * 16;
    float acc[8][4];
    #pragma unroll
    for (int j = 0; j < 8; j++)
        #pragma unroll
        for (int q = 0; q < 4; q++) acc[j][q] = 0.0f;

    const uint32_t a_row = (uint32_t)(m0 + (lane & 15)) * (AST * 2) + ((lane >> 4) << 4);
    const uint32_t b_row = (uint32_t)((lane & 7) + ((lane >> 4) << 3)) * (AST * 2)
                           + (((lane >> 3) & 1) << 4);
    const uint32_t AhiB = smem_u32(Ahi) + a_row;
    const uint32_t AloB = smem_u32(Alo) + a_row;
    const uint32_t BhiB = smem_u32(Bhi) + b_row;
    const uint32_t BloB = smem_u32(Blo) + b_row;

    #pragma unroll
    for (int kk = 0; kk < 8; kk++) {
        uint32_t ah0, ah1, ah2, ah3, al0, al1, al2, al3;
        ldsm4(ah0, ah1, ah2, ah3, AhiB + kk * 32);
        ldsm4(al0, al1, al2, al3, AloB + kk * 32);
        #pragma unroll
        for (int jj = 0; jj < 4; jj++) {
            uint32_t bh0, bh1, bh2, bh3, bl0, bl1, bl2, bl3;
            ldsm4(bh0, bh1, bh2, bh3, BhiB + jj * 16 * (AST * 2) + kk * 32);
            ldsm4(bl0, bl1, bl2, bl3, BloB + jj * 16 * (AST * 2) + kk * 32);
            mma16816(acc[2 * jj],     ah0, ah1, ah2, ah3, bh0, bh1);
            mma16816(acc[2 * jj + 1], ah0, ah1, ah2, ah3, bh2, bh3);
            mma16816(acc[2 * jj],     al0, al1, al2, al3, bh0, bh1);
            mma16816(acc[2 * jj + 1], al0, al1, al2, al3, bh2, bh3);
            mma16816(acc[2 * jj],     ah0, ah1, ah2, ah3, bl0, bl1);
            mma16816(acc[2 * jj + 1], ah0, ah1, ah2, ah3, bl2, bl3);
        }
    }
    __syncthreads();   // mainloop done everywhere before reusing Ahi/Alo as epi

    // ---- Epilogue: acc -> smem f32 tile (stride 72 words) -> coalesced STG ----
    {
        const int r0 = m0 + (lane >> 2);
        const int c0 = 2 * (lane & 3);
        #pragma unroll
        for (int j = 0; j < 8; j++) {
            int col = j * 8 + c0;
            float bb0 = bias[col], bb1 = bias[col + 1];
            float x0 = acc[j][0] + bb0, x1 = acc[j][1] + bb1;
            float x2 = acc[j][2] + bb0, x3 = acc[j][3] + bb1;
            if (RELU) {
                x0 = fmaxf(x0, 0.f); x1 = fmaxf(x1, 0.f);
                x2 = fmaxf(x2, 0.f); x3 = fmaxf(x3, 0.f);
            }
            *reinterpret_cast<float2*>(epi + r0 * EPI_STRIDE + col)       = make_float2(x0, x1);
            *reinterpret_cast<float2*>(epi + (r0 + 8) * EPI_STRIDE + col) = make_float2(x2, x3);
        }
    }
    __syncthreads();

    {
        float4* out4 = reinterpret_cast<float4*>(out);
        #pragma unroll
        for (int q = 0; q < 8; q++) {
            int idx = q * 256 + tid;          // 0..2047
            int node_l = idx >> 4;
            int c = idx & 15;
            int node = base + node_l;
            if (node < N_NODES)
                out4[(size_t)node * 16 + c] =
                    *reinterpret_cast<const float4*>(epi + node_l * EPI_STRIDE + c * 4);
        }
    }
}

extern "C" void kernel_launch(void* const* d_in, const int* in_sizes, int n_in,
                              void* d_out, int out_size)
{
    const float* x  = (const float*)d_in[0];
    const int*   ei = (const int*)  d_in[1];
    const float* W0 = (const float*)d_in[2];
    const float* b0 = (const float*)d_in[3];
    const float* W1 = (const float*)d_in[4];
    const float* b1 = (const float*)d_in[5];
    float* out = (float*)d_out;

    void *cnt_ptr = nullptr, *h1_ptr = nullptr, *wt_ptr = nullptr;
    cudaGetSymbolAddress(&cnt_ptr, g_cnt);
    cudaGetSymbolAddress(&h1_ptr,  g_h1);
    cudaGetSymbolAddress(&wt_ptr,  g_wt);
    float* h1 = (float*)h1_ptr;
    const unsigned short* wt = (const unsigned short*)wt_ptr;

    cudaFuncSetAttribute(xform_mma_kernel<true>,
                         cudaFuncAttributeMaxDynamicSharedMemorySize, SMEM_XF_TOTAL);
    cudaFuncSetAttribute(xform_mma_kernel<false>,
                         cudaFuncAttributeMaxDynamicSharedMemorySize, SMEM_XF_TOTAL);

    const int build_blocks  = (N_EDGES + 255) / 256;
    const int gather_blocks = N_NODES / 8;                     // exact
    const int xform_blocks  = (N_NODES + 127) / 128;           // 782

    cudaMemsetAsync(cnt_ptr, 0, N_NODES * sizeof(int));
    build_adj_kernel<<<build_blocks, 256>>>(ei);
    wprep_kernel<<<2, 256>>>(W0, W1);

    // ---- Layer 0 ----
    gather_kernel<<<gather_blocks, 256>>>(x);
    xform_mma_kernel<true><<<xform_blocks, 256, SMEM_XF_TOTAL>>>(
        x, wt + 0 * 8192, wt + 1 * 8192, b0, h1);

    // ---- Layer 1 ----
    gather_kernel<<<gather_blocks, 256>>>(h1);
    xform_mma_kernel<false><<<xform_blocks, 256, SMEM_XF_TOTAL>>>(
        h1, wt + 2 * 8192, wt + 3 * 8192, b1, out);
}